// round 2
// baseline (speedup 1.0000x reference)
#include <cuda_runtime.h>
#include <cstdint>
#include <cstddef>

// Problem constants (fixed by the reference)
#define BB    64      // batch
#define NNODE 1023    // nodes (perfect binary tree, 10 levels)
#define EE    256     // embedding dim
#define HH    512     // hidden dim
#define COLS  2048    // 4*H: [i | o | u | f]
#define KTOT  768     // E + H rows of combined weight

// -------- scratch (device globals; allocation-free) --------
__device__ float g_Wc[KTOT * COLS];                 // packed [W_iou | W_f], rows 0..255 = x-part, 256..767 = h-part
__device__ float g_bc[COLS];                        // packed bias
__device__ float g_xproj[(size_t)BB * NNODE * COLS]; // row g = node*B + b ; later overwritten in-place with act
__device__ float g_h[(size_t)BB * NNODE * HH];      // h per (node, b)
__device__ float g_c[(size_t)BB * NNODE * HH];      // c per (node, b)

// -------- pack combined weight/bias --------
__global__ void pack_kernel(const float* __restrict__ W_iou, const float* __restrict__ b_iou,
                            const float* __restrict__ W_f,  const float* __restrict__ b_f) {
    int idx = blockIdx.x * blockDim.x + threadIdx.x;
    int stride = gridDim.x * blockDim.x;
    const int total = KTOT * COLS;
    for (int t = idx; t < total; t += stride) {
        int k = t >> 11;        // / 2048
        int j = t & 2047;
        g_Wc[t] = (j < 3 * HH) ? W_iou[k * 3 * HH + j] : W_f[k * HH + (j - 3 * HH)];
    }
    if (idx < COLS) {
        g_bc[idx] = (idx < 3 * HH) ? b_iou[idx] : b_f[idx - 3 * HH];
    }
}

// -------- GEMM --------
// One block computes a 64(M) x 64(N) tile. Block row = one tree node across all 64 batches.
// XMODE=true : C[g, :] = emb[ast[b, node]] @ Wc[0:256, :] + bias          (K=256), g = node*64+b
// XMODE=false: C[g, :] += (h[2*node+1, b] + h[2*node+2, b]) @ Wc[256:768,:] (K=512), in-place on g_xproj
template <int KDIM, bool XMODE>
__global__ __launch_bounds__(256) void gemm_kernel(const float* __restrict__ emb,
                                                   const int*   __restrict__ ast,
                                                   int base) {
    const int node_off = blockIdx.y;          // node within level (XMODE: global node)
    const int bn       = blockIdx.x * 64;     // output column base
    const int tid      = threadIdx.x;

    __shared__ float As[16][68];   // [k][m], padded
    __shared__ float Bs[16][64];   // [k][n]

    // A-row source pointers: 4 m-rows (batches) per thread
    const int kload = tid & 15;
    const int m0    = tid >> 4;    // 0..15
    const float* aptr[4];
    if (XMODE) {
        #pragma unroll
        for (int i = 0; i < 4; i++) {
            int m = m0 + 16 * i;                       // batch b
            int tok = ast[m * NNODE + node_off];
            aptr[i] = emb + (size_t)tok * EE;
        }
    } else {
        int node = base + node_off;
        #pragma unroll
        for (int i = 0; i < 4; i++) {
            int m = m0 + 16 * i;
            size_t c1g = (size_t)(2 * node + 1) * BB + m;
            aptr[i] = g_h + c1g * HH;
        }
    }
    const int wrow_off = XMODE ? 0 : EE;

    const int nb  = tid & 63;
    const int kb4 = (tid >> 6) * 4;
    const int tx  = tid & 15;
    const int ty  = tid >> 4;

    float acc[4][4] = {};

    for (int kt = 0; kt < KDIM; kt += 16) {
        #pragma unroll
        for (int i = 0; i < 4; i++) {
            float v = aptr[i][kt + kload];
            if (!XMODE) v += aptr[i][(size_t)BB * HH + kt + kload];  // + second child
            As[kload][m0 + 16 * i] = v;
        }
        #pragma unroll
        for (int i = 0; i < 4; i++) {
            int k = kb4 + i;
            Bs[k][nb] = g_Wc[(size_t)(wrow_off + kt + k) * COLS + bn + nb];
        }
        __syncthreads();
        #pragma unroll
        for (int kk = 0; kk < 16; kk++) {
            float4 a4 = *(const float4*)&As[kk][ty * 4];
            float4 b4 = *(const float4*)&Bs[kk][tx * 4];
            float av[4] = {a4.x, a4.y, a4.z, a4.w};
            float bv[4] = {b4.x, b4.y, b4.z, b4.w};
            #pragma unroll
            for (int i = 0; i < 4; i++)
                #pragma unroll
                for (int j = 0; j < 4; j++)
                    acc[i][j] = fmaf(av[i], bv[j], acc[i][j]);
        }
        __syncthreads();
    }

    const int grow_base = (XMODE ? node_off : base + node_off) * BB;
    #pragma unroll
    for (int i = 0; i < 4; i++) {
        int m = ty * 4 + i;   // batch b
        float* dst = g_xproj + (size_t)(grow_base + m) * COLS + bn + tx * 4;
        float4 v;
        if (XMODE) {
            float4 bias = *(const float4*)&g_bc[bn + tx * 4];
            v.x = acc[i][0] + bias.x; v.y = acc[i][1] + bias.y;
            v.z = acc[i][2] + bias.z; v.w = acc[i][3] + bias.w;
        } else {
            float4 prev = *(const float4*)dst;
            v.x = acc[i][0] + prev.x; v.y = acc[i][1] + prev.y;
            v.z = acc[i][2] + prev.z; v.w = acc[i][3] + prev.w;
        }
        *(float4*)dst = v;
    }
}

// -------- gates: i,o,u,f -> c,h --------
__global__ void gate_kernel(int base, int L, int leaf, float* __restrict__ out) {
    int idx = blockIdx.x * blockDim.x + threadIdx.x;
    int total = L * BB * HH;
    if (idx >= total) return;
    int k = idx & (HH - 1);
    int r = idx >> 9;                   // / 512
    int g = base * BB + r;
    const float* act = g_xproj + (size_t)g * COLS;
    float xi = act[k];
    float xo = act[HH + k];
    float xu = act[2 * HH + k];
    float xf = act[3 * HH + k];
    float ig = 1.f / (1.f + expf(-xi));
    float og = 1.f / (1.f + expf(-xo));
    float ug = tanhf(xu);
    float fg = 1.f / (1.f + expf(-xf));
    float cs = 0.f;
    if (!leaf) {
        int node = base + (r >> 6);     // r / 64
        int b    = r & 63;
        size_t c1 = ((size_t)(2 * node + 1) * BB + b) * HH + k;
        cs = g_c[c1] + g_c[c1 + (size_t)BB * HH];
    }
    float c = fmaf(fg, cs, ig * ug);
    float h = og * tanhf(c);
    g_h[(size_t)g * HH + k] = h;
    g_c[(size_t)g * HH + k] = c;
    if (out) out[idx] = h;              // only base==0: idx = b*512+k
}

extern "C" void kernel_launch(void* const* d_in, const int* in_sizes, int n_in,
                              void* d_out, int out_size) {
    const int*   ast   = (const int*)d_in[0];
    // d_in[1] = parent (int64) — structurally (i-1)/2, unused
    const float* emb   = (const float*)d_in[2];
    const float* W_iou = (const float*)d_in[3];
    const float* b_iou = (const float*)d_in[4];
    const float* W_f   = (const float*)d_in[5];
    const float* b_f   = (const float*)d_in[6];
    float* out = (float*)d_out;

    (void)in_sizes; (void)n_in; (void)out_size;

    pack_kernel<<<512, 256>>>(W_iou, b_iou, W_f, b_f);

    // x-projection for all nodes: M = 1023 nodes * 64 batch, K=256, N=2048
    {
        dim3 grid(COLS / 64, NNODE);
        gemm_kernel<EE, true><<<grid, 256>>>(emb, ast, 0);
    }

    // level 9: leaves (hsum = csum = 0) — gates straight from xproj
    {
        int base = 511, L = 512;
        int total = L * BB * HH;
        gate_kernel<<<(total + 255) / 256, 256>>>(base, L, 1, nullptr);
    }

    // levels 8..0: recurrent GEMM (in-place) + gates
    for (int d = 8; d >= 0; d--) {
        int L = 1 << d;
        int base = L - 1;
        dim3 grid(COLS / 64, L);
        gemm_kernel<HH, false><<<grid, 256>>>(nullptr, nullptr, base);
        int total = L * BB * HH;
        gate_kernel<<<(total + 255) / 256, 256>>>(base, L, 0, (d == 0) ? out : nullptr);
    }
}

// round 4
// speedup vs baseline: 2.9665x; 2.9665x over previous
#include <cuda_runtime.h>
#include <cuda_bf16.h>
#include <cstdint>
#include <cstddef>

// ---------------- problem constants ----------------
#define BB    64
#define NNODE 1023
#define EE    256
#define HH    512
#define COLS  2048      // 4*H gate columns [i|o|u|f]
#define KTOT  768       // E + H
#define VOCAB 2000
#define MAXMR 16384     // max rows in a recurrent level (level 8: 256*64)

// ---------------- device scratch (allocation-free) ----------------
__device__ __nv_bfloat16 g_WTh[(size_t)COLS * KTOT];   // W^T hi  [n][k]
__device__ __nv_bfloat16 g_WTl[(size_t)COLS * KTOT];   // W^T lo
__device__ float         g_bc[COLS];                   // packed bias
__device__ __nv_bfloat16 g_Eh[2048 * EE];              // emb_table split (padded to 2048 rows)
__device__ __nv_bfloat16 g_El[2048 * EE];
__device__ float         g_ptab[(size_t)VOCAB * COLS]; // emb_table @ Wx + bias
__device__ __nv_bfloat16 g_Ah[(size_t)MAXMR * HH];     // hsum split (recurrent A)
__device__ __nv_bfloat16 g_Al[(size_t)MAXMR * HH];
__device__ float         g_h[(size_t)BB * NNODE * HH];
__device__ float         g_c[(size_t)BB * NNODE * HH];

// ---------------- helpers ----------------
__device__ __forceinline__ uint32_t smem_u32(const void* p) {
    uint32_t a;
    asm("{ .reg .u64 t; cvta.to.shared.u64 t, %1; cvt.u32.u64 %0, t; }" : "=r"(a) : "l"(p));
    return a;
}
__device__ __forceinline__ void cp_async16(uint32_t saddr, const void* g) {
    asm volatile("cp.async.cg.shared.global [%0], [%1], 16;"
                 :: "r"(saddr), "l"(__cvta_generic_to_global(g)) : "memory");
}
#define CP_COMMIT() asm volatile("cp.async.commit_group;" ::: "memory")
#define CP_WAIT(n)  asm volatile("cp.async.wait_group %0;" :: "n"(n) : "memory")

#define LDSM4(r, addr) \
    asm volatile("ldmatrix.sync.aligned.m8n8.x4.shared.b16 {%0,%1,%2,%3}, [%4];" \
        : "=r"((r)[0]), "=r"((r)[1]), "=r"((r)[2]), "=r"((r)[3]) : "r"(addr))

#define MMA16816(d, a, b) \
    asm volatile("mma.sync.aligned.m16n8k16.row.col.f32.bf16.bf16.f32 " \
        "{%0,%1,%2,%3}, {%4,%5,%6,%7}, {%8,%9}, {%0,%1,%2,%3};" \
        : "+f"((d)[0]), "+f"((d)[1]), "+f"((d)[2]), "+f"((d)[3]) \
        : "r"((a)[0]), "r"((a)[1]), "r"((a)[2]), "r"((a)[3]), "r"((b)[0]), "r"((b)[1]))

__device__ __forceinline__ void split2(float v, __nv_bfloat16& hi, __nv_bfloat16& lo) {
    hi = __float2bfloat16(v);
    lo = __float2bfloat16(v - __bfloat162float(hi));
}
__device__ __forceinline__ float sigf(float x) { return 1.f / (1.f + expf(-x)); }

// ---------------- pack W^T hi/lo + bias ----------------
__global__ void pack_kernel(const float* __restrict__ W_iou, const float* __restrict__ b_iou,
                            const float* __restrict__ W_f,  const float* __restrict__ b_f) {
    int idx = blockIdx.x * blockDim.x + threadIdx.x;
    int stride = gridDim.x * blockDim.x;
    const int total = COLS * KTOT;
    for (int t = idx; t < total; t += stride) {
        int n = t / KTOT;
        int k = t - n * KTOT;
        float w = (n < 3 * HH) ? W_iou[k * 3 * HH + n] : W_f[k * HH + (n - 3 * HH)];
        __nv_bfloat16 hi, lo; split2(w, hi, lo);
        g_WTh[t] = hi; g_WTl[t] = lo;
    }
    if (idx < COLS)
        g_bc[idx] = (idx < 3 * HH) ? b_iou[idx] : b_f[idx - 3 * HH];
}

// ---------------- split emb table (pad to 2048 rows) ----------------
__global__ void esplit_kernel(const float* __restrict__ emb) {
    int idx = blockIdx.x * blockDim.x + threadIdx.x;   // over 2048*256
    if (idx >= 2048 * EE) return;
    int r = idx >> 8, k = idx & 255;
    float v = (r < VOCAB) ? emb[r * EE + k] : 0.f;
    __nv_bfloat16 hi, lo; split2(v, hi, lo);
    g_Eh[idx] = hi; g_El[idx] = lo;
}

// ---------------- hsum (children h) + split ----------------
__global__ void hsum_kernel(int base, int L, int mpad) {
    int idx = blockIdx.x * blockDim.x + threadIdx.x;   // over mpad*512
    if (idx >= mpad * HH) return;
    int r = idx >> 9;
    int k = idx & (HH - 1);
    float v = 0.f;
    if (r < 64 * L) {
        int node = base + (r >> 6), b = r & 63;
        size_t c1 = ((size_t)(2 * node + 1) * BB + b) * HH + k;
        v = g_h[c1] + g_h[c1 + (size_t)BB * HH];
    }
    __nv_bfloat16 hi, lo; split2(v, hi, lo);
    g_Ah[idx] = hi;
    g_Al[idx] = lo;
}

// ---------------- leaf gates (cs = 0) ----------------
__global__ void leaf_gate(const int* __restrict__ ast) {
    int idx = blockIdx.x * blockDim.x + threadIdx.x;   // over 512*64*512
    if (idx >= 512 * 64 * HH) return;
    int k = idx & (HH - 1);
    int r = idx >> 9;                                  // 0..32767
    int node = 511 + (r >> 6), b = r & 63;
    int tok = ast[b * NNODE + node];
    const float* p = g_ptab + (size_t)tok * COLS;
    float ig = sigf(p[k]);
    float og = sigf(p[HH + k]);
    float ug = tanhf(p[2 * HH + k]);
    float c = ig * ug;
    float h = og * tanhf(c);
    size_t gi = (size_t)(511 * 64 + r) * HH + k;
    g_h[gi] = h;
    g_c[gi] = c;
}

// ---------------- bf16x3 mma.sync GEMM ----------------
// TABLE=true : g_ptab[0:2000, n0:n0+128] = Eh/El @ W[0:256] + bias     (K=256)
// TABLE=false: fused epilogue: act = ptab[tok] + hsum@W[256:768]; gates -> h,c (K=512)
//              CTA covers 32 k-values x 4 gates (cols gate*512 + kbase + 0..31)
static constexpr int STAGE_BYTES = 40960;   // 4 arrays x 128 rows x 80B
static constexpr int NSTAGE = 4;
static constexpr int SMEM_TOTAL = STAGE_BYTES * NSTAGE;   // 160KB

template <int KDIM, bool TABLE>
__global__ __launch_bounds__(256, 1)
void mma_gemm(const int* __restrict__ ast, int base, int mrows, float* __restrict__ out) {
    extern __shared__ char smem[];
    const uint32_t sbase = smem_u32(smem);
    const int tid = threadIdx.x;
    const int lane = tid & 31, wid = tid >> 5;
    const int wm = wid >> 2, wn = wid & 3;      // warp grid 2(m) x 4(n)
    const int mtile = blockIdx.y;
    const int n0    = blockIdx.x * 128;         // TABLE: plain col base
    const int kbase = blockIdx.x * 32;          // FUSED: k base within H
    constexpr int NC = KDIM / 32;
    constexpr int KOFF = TABLE ? 0 : EE;

    const __nv_bfloat16* gAh = (TABLE ? g_Eh : g_Ah) + (size_t)(mtile * 128) * KDIM;
    const __nv_bfloat16* gAl = (TABLE ? g_El : g_Al) + (size_t)(mtile * 128) * KDIM;

    // ---- stage loader: A(hi/lo) 128x32, B(hi/lo) 128x32 ----
    auto load_stage = [&](int kc, int s) {
        const uint32_t sb = sbase + s * STAGE_BYTES;
        #pragma unroll
        for (int i = 0; i < 2; i++) {
            int cid = tid + i * 256;                 // 0..511
            int row = cid >> 2, ch = cid & 3;
            uint32_t so = row * 80 + ch * 16;
            const size_t ga = (size_t)row * KDIM + kc * 32 + ch * 8;
            cp_async16(sb + so,          gAh + ga);
            cp_async16(sb + 10240 + so,  gAl + ga);
        }
        #pragma unroll
        for (int i = 0; i < 2; i++) {
            int cid = tid + i * 256;
            int j = cid >> 2, ch = cid & 3;
            int gn = TABLE ? (n0 + j) : (((j >> 5) << 9) + kbase + (j & 31));
            const size_t gb = (size_t)gn * KTOT + KOFF + kc * 32 + ch * 8;
            cp_async16(sb + 20480 + j * 80 + ch * 16, g_WTh + gb);
            cp_async16(sb + 30720 + j * 80 + ch * 16, g_WTl + gb);
        }
    };

    float acc[4][4][4] = {};

    load_stage(0, 0); CP_COMMIT();
    load_stage(1, 1); CP_COMMIT();
    load_stage(2, 2); CP_COMMIT();

    for (int c = 0; c < NC; c++) {
        CP_WAIT(2);
        __syncthreads();
        if (c + 3 < NC) load_stage(c + 3, (c + 3) & 3);
        CP_COMMIT();

        const uint32_t sb = sbase + (c & 3) * STAGE_BYTES;
        #pragma unroll
        for (int k16 = 0; k16 < 2; k16++) {
            uint32_t ah[4][4], al[4][4], bh[4][2], bl[4][2];
            // A fragments: 4 m-tiles of 16
            #pragma unroll
            for (int mt = 0; mt < 4; mt++) {
                uint32_t addr = sb + (wm * 64 + mt * 16 + (lane & 15)) * 80
                              + k16 * 32 + ((lane >> 4) & 1) * 16;
                LDSM4(ah[mt], addr);
                LDSM4(al[mt], addr + 10240);
            }
            // B fragments: 2 x4-loads cover 4 n-tiles of 8
            #pragma unroll
            for (int bt = 0; bt < 2; bt++) {
                int nrow = wn * 32 + bt * 16 + ((lane >> 4) & 1) * 8 + (lane & 7);
                uint32_t addr = sb + 20480 + nrow * 80 + k16 * 32 + ((lane >> 3) & 1) * 16;
                uint32_t t4[4];
                LDSM4(t4, addr);
                bh[2 * bt][0] = t4[0]; bh[2 * bt][1] = t4[1];
                bh[2 * bt + 1][0] = t4[2]; bh[2 * bt + 1][1] = t4[3];
                LDSM4(t4, addr + 10240);
                bl[2 * bt][0] = t4[0]; bl[2 * bt][1] = t4[1];
                bl[2 * bt + 1][0] = t4[2]; bl[2 * bt + 1][1] = t4[3];
            }
            #pragma unroll
            for (int mt = 0; mt < 4; mt++)
                #pragma unroll
                for (int nt = 0; nt < 4; nt++) {
                    MMA16816(acc[mt][nt], ah[mt], bh[nt]);
                    MMA16816(acc[mt][nt], ah[mt], bl[nt]);
                    MMA16816(acc[mt][nt], al[mt], bh[nt]);
                }
        }
    }

    if (TABLE) {
        // direct frag store: ptab = acc + bias
        #pragma unroll
        for (int mt = 0; mt < 4; mt++) {
            #pragma unroll
            for (int nt = 0; nt < 4; nt++) {
                int col = n0 + wn * 32 + nt * 8 + (lane & 3) * 2;
                int r0 = mtile * 128 + wm * 64 + mt * 16 + (lane >> 2);
                float b0 = g_bc[col], b1 = g_bc[col + 1];
                if (r0 < mrows) {
                    float2 v = make_float2(acc[mt][nt][0] + b0, acc[mt][nt][1] + b1);
                    *(float2*)&g_ptab[(size_t)r0 * COLS + col] = v;
                }
                if (r0 + 8 < mrows) {
                    float2 v = make_float2(acc[mt][nt][2] + b0, acc[mt][nt][3] + b1);
                    *(float2*)&g_ptab[(size_t)(r0 + 8) * COLS + col] = v;
                }
            }
        }
    } else {
        // stage acc -> smem, then fused gate epilogue
        __syncthreads();
        float* fbuf = (float*)smem;                  // [128][132]
        #pragma unroll
        for (int mt = 0; mt < 4; mt++) {
            #pragma unroll
            for (int nt = 0; nt < 4; nt++) {
                int col = wn * 32 + nt * 8 + (lane & 3) * 2;
                int r0 = wm * 64 + mt * 16 + (lane >> 2);
                fbuf[r0 * 132 + col]       = acc[mt][nt][0];
                fbuf[r0 * 132 + col + 1]   = acc[mt][nt][1];
                fbuf[(r0 + 8) * 132 + col]     = acc[mt][nt][2];
                fbuf[(r0 + 8) * 132 + col + 1] = acc[mt][nt][3];
            }
        }
        __syncthreads();
        #pragma unroll
        for (int i = 0; i < 16; i++) {
            int e = tid + i * 256;                   // 0..4095
            int r = e >> 5, q = e & 31;
            int g = mtile * 128 + r;
            if (g >= mrows) continue;
            int node = base + (g >> 6), b = g & 63;
            int tok = ast[b * NNODE + node];
            int k = kbase + q;
            const float* p = g_ptab + (size_t)tok * COLS + k;
            const float* fr = fbuf + r * 132 + q;
            float xi = fr[0]   + p[0];
            float xo = fr[32]  + p[HH];
            float xu = fr[64]  + p[2 * HH];
            float xf = fr[96]  + p[3 * HH];
            size_t c1 = ((size_t)(2 * node + 1) * BB + b) * HH + k;
            float cs = g_c[c1] + g_c[c1 + (size_t)BB * HH];
            float ig = sigf(xi), og = sigf(xo), ug = tanhf(xu), fg = sigf(xf);
            float cc = fmaf(fg, cs, ig * ug);
            float hh = og * tanhf(cc);
            size_t gi = ((size_t)base * 64 + g) * HH + k;
            g_h[gi] = hh;
            g_c[gi] = cc;
            if (out) out[(size_t)g * HH + k] = hh;
        }
    }
}

// ---------------- launch ----------------
extern "C" void kernel_launch(void* const* d_in, const int* in_sizes, int n_in,
                              void* d_out, int out_size) {
    const int*   ast   = (const int*)d_in[0];
    // d_in[1] = parent (structurally (i-1)/2, unused)
    const float* emb   = (const float*)d_in[2];
    const float* W_iou = (const float*)d_in[3];
    const float* b_iou = (const float*)d_in[4];
    const float* W_f   = (const float*)d_in[5];
    const float* b_f   = (const float*)d_in[6];
    float* out = (float*)d_out;
    (void)in_sizes; (void)n_in; (void)out_size;

    cudaFuncSetAttribute(mma_gemm<EE, true>,  cudaFuncAttributeMaxDynamicSharedMemorySize, SMEM_TOTAL);
    cudaFuncSetAttribute(mma_gemm<HH, false>, cudaFuncAttributeMaxDynamicSharedMemorySize, SMEM_TOTAL);

    pack_kernel<<<512, 256>>>(W_iou, b_iou, W_f, b_f);
    esplit_kernel<<<(2048 * EE + 255) / 256, 256>>>(emb);

    // ptab = emb_table @ Wx + bias : M=2000 (pad 2048), K=256, N=2048
    {
        dim3 grid(COLS / 128, 16);
        mma_gemm<EE, true><<<grid, 256, SMEM_TOTAL>>>(nullptr, 0, VOCAB, nullptr);
    }

    // leaves
    leaf_gate<<<(512 * 64 * HH + 255) / 256, 256>>>(ast);

    // levels 8..0: hsum-split -> fused GEMM+gates
    for (int d = 8; d >= 0; d--) {
        int L = 1 << d;
        int base = L - 1;
        int M = 64 * L;
        int mtiles = (M + 127) / 128;
        int mpad = mtiles * 128;
        hsum_kernel<<<(mpad * HH + 255) / 256, 256>>>(base, L, mpad);
        dim3 grid(HH / 32, mtiles);
        mma_gemm<HH, false><<<grid, 256, SMEM_TOTAL>>>(ast, base, M, (d == 0) ? out : nullptr);
    }
}

// round 5
// speedup vs baseline: 3.6492x; 1.2301x over previous
#include <cuda_runtime.h>
#include <cuda_bf16.h>
#include <cstdint>
#include <cstddef>

// ---------------- problem constants ----------------
#define BB    64
#define NNODE 1023
#define EE    256
#define HH    512
#define COLS  2048      // 4*H gate columns [i|o|u|f]
#define KTOT  768       // E + H
#define VOCAB 2000
#define MAXMR 16384     // max rows in a recurrent level (level 8: 256*64)

// ---------------- device scratch (allocation-free) ----------------
__device__ __nv_bfloat16 g_WTh[(size_t)COLS * KTOT];   // W^T hi  [n][k]
__device__ __nv_bfloat16 g_WTl[(size_t)COLS * KTOT];   // W^T lo
__device__ float         g_bc[COLS];                   // packed bias
__device__ __nv_bfloat16 g_Eh[2048 * EE];              // emb_table split (padded to 2048 rows)
__device__ __nv_bfloat16 g_El[2048 * EE];
__device__ float         g_ptab[(size_t)VOCAB * COLS]; // emb_table @ Wx + bias
__device__ __nv_bfloat16 g_Ah[(size_t)MAXMR * HH];     // hsum split (recurrent A)
__device__ __nv_bfloat16 g_Al[(size_t)MAXMR * HH];
__device__ float         g_h[(size_t)BB * NNODE * HH];
__device__ float         g_c[(size_t)BB * NNODE * HH];

// ---------------- helpers ----------------
__device__ __forceinline__ uint32_t smem_u32(const void* p) {
    uint32_t a;
    asm("{ .reg .u64 t; cvta.to.shared.u64 t, %1; cvt.u32.u64 %0, t; }" : "=r"(a) : "l"(p));
    return a;
}
__device__ __forceinline__ void cp_async16(uint32_t saddr, const void* g) {
    asm volatile("cp.async.cg.shared.global [%0], [%1], 16;"
                 :: "r"(saddr), "l"(__cvta_generic_to_global(g)) : "memory");
}
#define CP_COMMIT() asm volatile("cp.async.commit_group;" ::: "memory")
#define CP_WAIT(n)  asm volatile("cp.async.wait_group %0;" :: "n"(n) : "memory")

#define LDSM4(r, addr) \
    asm volatile("ldmatrix.sync.aligned.m8n8.x4.shared.b16 {%0,%1,%2,%3}, [%4];" \
        : "=r"((r)[0]), "=r"((r)[1]), "=r"((r)[2]), "=r"((r)[3]) : "r"(addr))

#define MMA16816(d, a, b) \
    asm volatile("mma.sync.aligned.m16n8k16.row.col.f32.bf16.bf16.f32 " \
        "{%0,%1,%2,%3}, {%4,%5,%6,%7}, {%8,%9}, {%0,%1,%2,%3};" \
        : "+f"((d)[0]), "+f"((d)[1]), "+f"((d)[2]), "+f"((d)[3]) \
        : "r"((a)[0]), "r"((a)[1]), "r"((a)[2]), "r"((a)[3]), "r"((b)[0]), "r"((b)[1]))

__device__ __forceinline__ void split2(float v, __nv_bfloat16& hi, __nv_bfloat16& lo) {
    hi = __float2bfloat16(v);
    lo = __float2bfloat16(v - __bfloat162float(hi));
}
// fast gates (MUFU-based): ~1e-7 rel error
__device__ __forceinline__ float sigf(float x)  { return __fdividef(1.f, 1.f + __expf(-x)); }
__device__ __forceinline__ float tanhff(float x){ return __fdividef(2.f, 1.f + __expf(-2.f * x)) - 1.f; }

// ---------------- pack W^T hi/lo + bias ----------------
__global__ void pack_kernel(const float* __restrict__ W_iou, const float* __restrict__ b_iou,
                            const float* __restrict__ W_f,  const float* __restrict__ b_f) {
    int idx = blockIdx.x * blockDim.x + threadIdx.x;
    int stride = gridDim.x * blockDim.x;
    const int total = COLS * KTOT;
    for (int t = idx; t < total; t += stride) {
        int n = t / KTOT;
        int k = t - n * KTOT;
        float w = (n < 3 * HH) ? W_iou[k * 3 * HH + n] : W_f[k * HH + (n - 3 * HH)];
        __nv_bfloat16 hi, lo; split2(w, hi, lo);
        g_WTh[t] = hi; g_WTl[t] = lo;
    }
    if (idx < COLS)
        g_bc[idx] = (idx < 3 * HH) ? b_iou[idx] : b_f[idx - 3 * HH];
}

// ---------------- split emb table (pad to 2048 rows) ----------------
__global__ void esplit_kernel(const float* __restrict__ emb) {
    int idx = blockIdx.x * blockDim.x + threadIdx.x;   // over 2048*256
    if (idx >= 2048 * EE) return;
    int r = idx >> 8, k = idx & 255;
    float v = (r < VOCAB) ? emb[r * EE + k] : 0.f;
    __nv_bfloat16 hi, lo; split2(v, hi, lo);
    g_Eh[idx] = hi; g_El[idx] = lo;
}

// ---------------- hsum (children h) + split ----------------
__global__ void hsum_kernel(int base, int L, int mpad) {
    int idx = blockIdx.x * blockDim.x + threadIdx.x;   // over mpad*512
    if (idx >= mpad * HH) return;
    int r = idx >> 9;
    int k = idx & (HH - 1);
    float v = 0.f;
    if (r < 64 * L) {
        int node = base + (r >> 6), b = r & 63;
        size_t c1 = ((size_t)(2 * node + 1) * BB + b) * HH + k;
        v = g_h[c1] + g_h[c1 + (size_t)BB * HH];
    }
    __nv_bfloat16 hi, lo; split2(v, hi, lo);
    g_Ah[idx] = hi;
    g_Al[idx] = lo;
}

// ---------------- leaf gates (cs = 0) ----------------
__global__ void leaf_gate(const int* __restrict__ ast) {
    int idx = blockIdx.x * blockDim.x + threadIdx.x;   // over 512*64*512
    if (idx >= 512 * 64 * HH) return;
    int k = idx & (HH - 1);
    int r = idx >> 9;                                  // 0..32767
    int node = 511 + (r >> 6), b = r & 63;
    int tok = ast[b * NNODE + node];
    const float* p = g_ptab + (size_t)tok * COLS;
    float ig = sigf(p[k]);
    float og = sigf(p[HH + k]);
    float ug = tanhff(p[2 * HH + k]);
    float c = ig * ug;
    float h = og * tanhff(c);
    size_t gi = (size_t)(511 * 64 + r) * HH + k;
    g_h[gi] = h;
    g_c[gi] = c;
}

// ---------------- bf16x3 mma.sync GEMM (512 threads, 4x4 warps, 32x32 warptile) ----------------
// TABLE=true : g_ptab[0:2000, n0:n0+128] = Eh/El @ W[0:256] + bias     (K=256)
// TABLE=false: fused epilogue: act = ptab[tok] + hsum@W[256:768]; gates -> h,c (K=512)
//              CTA covers 32 k-values x 4 gates (cols gate*512 + kbase + 0..31)
static constexpr int STAGE_BYTES = 40960;   // 4 arrays x 128 rows x 80B
static constexpr int SMEM_TOTAL = STAGE_BYTES * 4;   // 160KB

template <int KDIM, bool TABLE>
__global__ __launch_bounds__(512, 1)
void mma_gemm(const int* __restrict__ ast, int base, int mrows, float* __restrict__ out) {
    extern __shared__ char smem[];
    const uint32_t sbase = smem_u32(smem);
    const int tid = threadIdx.x;
    const int lane = tid & 31, wid = tid >> 5;
    const int wm = wid >> 2, wn = wid & 3;      // warp grid 4(m) x 4(n)
    const int mtile = blockIdx.y;
    const int n0    = blockIdx.x * 128;         // TABLE: plain col base
    const int kbase = blockIdx.x * 32;          // FUSED: k base within H
    constexpr int NC = KDIM / 32;
    constexpr int KOFF = TABLE ? 0 : EE;

    const __nv_bfloat16* gAh = (TABLE ? g_Eh : g_Ah) + (size_t)(mtile * 128) * KDIM;
    const __nv_bfloat16* gAl = (TABLE ? g_El : g_Al) + (size_t)(mtile * 128) * KDIM;

    // ---- stage loader: A(hi/lo) 128x32, B(hi/lo) 128x32; 1 chunk each per thread ----
    auto load_stage = [&](int kc, int s) {
        const uint32_t sb = sbase + s * STAGE_BYTES;
        {
            int row = tid >> 2, ch = tid & 3;
            uint32_t so = row * 80 + ch * 16;
            const size_t ga = (size_t)row * KDIM + kc * 32 + ch * 8;
            cp_async16(sb + so,          gAh + ga);
            cp_async16(sb + 10240 + so,  gAl + ga);
        }
        {
            int j = tid >> 2, ch = tid & 3;
            int gn = TABLE ? (n0 + j) : (((j >> 5) << 9) + kbase + (j & 31));
            const size_t gb = (size_t)gn * KTOT + KOFF + kc * 32 + ch * 8;
            cp_async16(sb + 20480 + j * 80 + ch * 16, g_WTh + gb);
            cp_async16(sb + 30720 + j * 80 + ch * 16, g_WTl + gb);
        }
    };

    float acc[2][4][4] = {};

    load_stage(0, 0); CP_COMMIT();
    load_stage(1, 1); CP_COMMIT();
    load_stage(2, 2); CP_COMMIT();

    for (int c = 0; c < NC; c++) {
        CP_WAIT(2);
        __syncthreads();
        if (c + 3 < NC) load_stage(c + 3, (c + 3) & 3);
        CP_COMMIT();

        const uint32_t sb = sbase + (c & 3) * STAGE_BYTES;
        #pragma unroll
        for (int k16 = 0; k16 < 2; k16++) {
            uint32_t ah[2][4], al[2][4], bh[4][2], bl[4][2];
            // A fragments: 2 m-tiles of 16 rows
            #pragma unroll
            for (int mt = 0; mt < 2; mt++) {
                uint32_t addr = sb + (wm * 32 + mt * 16 + (lane & 15)) * 80
                              + k16 * 32 + ((lane >> 4) & 1) * 16;
                LDSM4(ah[mt], addr);
                LDSM4(al[mt], addr + 10240);
            }
            // B fragments: 2 x4-loads per split cover 4 n-tiles of 8
            #pragma unroll
            for (int bt = 0; bt < 2; bt++) {
                int nrow = wn * 32 + bt * 16 + ((lane >> 4) & 1) * 8 + (lane & 7);
                uint32_t addr = sb + 20480 + nrow * 80 + k16 * 32 + ((lane >> 3) & 1) * 16;
                uint32_t t4[4];
                LDSM4(t4, addr);
                bh[2 * bt][0] = t4[0]; bh[2 * bt][1] = t4[1];
                bh[2 * bt + 1][0] = t4[2]; bh[2 * bt + 1][1] = t4[3];
                LDSM4(t4, addr + 10240);
                bl[2 * bt][0] = t4[0]; bl[2 * bt][1] = t4[1];
                bl[2 * bt + 1][0] = t4[2]; bl[2 * bt + 1][1] = t4[3];
            }
            #pragma unroll
            for (int mt = 0; mt < 2; mt++)
                #pragma unroll
                for (int nt = 0; nt < 4; nt++) {
                    MMA16816(acc[mt][nt], ah[mt], bh[nt]);
                    MMA16816(acc[mt][nt], ah[mt], bl[nt]);
                    MMA16816(acc[mt][nt], al[mt], bh[nt]);
                }
        }
    }

    if (TABLE) {
        // direct frag store: ptab = acc + bias
        #pragma unroll
        for (int mt = 0; mt < 2; mt++) {
            #pragma unroll
            for (int nt = 0; nt < 4; nt++) {
                int col = n0 + wn * 32 + nt * 8 + (lane & 3) * 2;
                int r0 = mtile * 128 + wm * 32 + mt * 16 + (lane >> 2);
                float b0 = g_bc[col], b1 = g_bc[col + 1];
                if (r0 < mrows) {
                    float2 v = make_float2(acc[mt][nt][0] + b0, acc[mt][nt][1] + b1);
                    *(float2*)&g_ptab[(size_t)r0 * COLS + col] = v;
                }
                if (r0 + 8 < mrows) {
                    float2 v = make_float2(acc[mt][nt][2] + b0, acc[mt][nt][3] + b1);
                    *(float2*)&g_ptab[(size_t)(r0 + 8) * COLS + col] = v;
                }
            }
        }
    } else {
        // stage acc -> smem, then fused gate epilogue
        __syncthreads();
        float* fbuf = (float*)smem;                  // [128][132]
        #pragma unroll
        for (int mt = 0; mt < 2; mt++) {
            #pragma unroll
            for (int nt = 0; nt < 4; nt++) {
                int col = wn * 32 + nt * 8 + (lane & 3) * 2;
                int r0 = wm * 32 + mt * 16 + (lane >> 2);
                fbuf[r0 * 132 + col]       = acc[mt][nt][0];
                fbuf[r0 * 132 + col + 1]   = acc[mt][nt][1];
                fbuf[(r0 + 8) * 132 + col]     = acc[mt][nt][2];
                fbuf[(r0 + 8) * 132 + col + 1] = acc[mt][nt][3];
            }
        }
        __syncthreads();
        #pragma unroll
        for (int i = 0; i < 8; i++) {
            int e = tid + i * 512;                   // 0..4095
            int r = e >> 5, q = e & 31;
            int g = mtile * 128 + r;
            if (g >= mrows) continue;
            int node = base + (g >> 6), b = g & 63;
            int tok = ast[b * NNODE + node];
            int k = kbase + q;
            const float* p = g_ptab + (size_t)tok * COLS + k;
            const float* fr = fbuf + r * 132 + q;
            float xi = fr[0]   + p[0];
            float xo = fr[32]  + p[HH];
            float xu = fr[64]  + p[2 * HH];
            float xf = fr[96]  + p[3 * HH];
            size_t c1 = ((size_t)(2 * node + 1) * BB + b) * HH + k;
            float cs = g_c[c1] + g_c[c1 + (size_t)BB * HH];
            float ig = sigf(xi), og = sigf(xo), ug = tanhff(xu), fg = sigf(xf);
            float cc = fmaf(fg, cs, ig * ug);
            float hh = og * tanhff(cc);
            size_t gi = ((size_t)base * 64 + g) * HH + k;
            g_h[gi] = hh;
            g_c[gi] = cc;
            if (out) out[(size_t)g * HH + k] = hh;
        }
    }
}

// ---------------- launch ----------------
extern "C" void kernel_launch(void* const* d_in, const int* in_sizes, int n_in,
                              void* d_out, int out_size) {
    const int*   ast   = (const int*)d_in[0];
    // d_in[1] = parent (structurally (i-1)/2, unused)
    const float* emb   = (const float*)d_in[2];
    const float* W_iou = (const float*)d_in[3];
    const float* b_iou = (const float*)d_in[4];
    const float* W_f   = (const float*)d_in[5];
    const float* b_f   = (const float*)d_in[6];
    float* out = (float*)d_out;
    (void)in_sizes; (void)n_in; (void)out_size;

    cudaFuncSetAttribute(mma_gemm<EE, true>,  cudaFuncAttributeMaxDynamicSharedMemorySize, SMEM_TOTAL);
    cudaFuncSetAttribute(mma_gemm<HH, false>, cudaFuncAttributeMaxDynamicSharedMemorySize, SMEM_TOTAL);

    pack_kernel<<<512, 256>>>(W_iou, b_iou, W_f, b_f);
    esplit_kernel<<<(2048 * EE + 255) / 256, 256>>>(emb);

    // ptab = emb_table @ Wx + bias : M=2000 (pad 2048), K=256, N=2048
    {
        dim3 grid(COLS / 128, 16);
        mma_gemm<EE, true><<<grid, 512, SMEM_TOTAL>>>(nullptr, 0, VOCAB, nullptr);
    }

    // leaves
    leaf_gate<<<(512 * 64 * HH + 255) / 256, 256>>>(ast);

    // levels 8..0: hsum-split -> fused GEMM+gates
    for (int d = 8; d >= 0; d--) {
        int L = 1 << d;
        int base = L - 1;
        int M = 64 * L;
        int mtiles = (M + 127) / 128;
        int mpad = mtiles * 128;
        hsum_kernel<<<(mpad * HH + 255) / 256, 256>>>(base, L, mpad);
        dim3 grid(HH / 32, mtiles);
        mma_gemm<HH, false><<<grid, 512, SMEM_TOTAL>>>(ast, base, M, (d == 0) ? out : nullptr);
    }
}

// round 6
// speedup vs baseline: 4.4734x; 1.2259x over previous
#include <cuda_runtime.h>
#include <cuda_bf16.h>
#include <cstdint>
#include <cstddef>

// ---------------- problem constants ----------------
#define BB    64
#define NNODE 1023
#define EE    256
#define HH    512
#define COLS  2048      // 4*H gate columns [i|o|u|f]
#define KTOT  768       // E + H
#define VOCAB 2000
#define MAXMR 16384     // max rows in a recurrent level (level 8: 256*64)

// ---------------- device scratch (allocation-free) ----------------
__device__ __nv_bfloat16 g_WTh[(size_t)COLS * KTOT];   // W^T hi  [n][k]
__device__ __nv_bfloat16 g_WTl[(size_t)COLS * KTOT];   // W^T lo
__device__ float         g_bc[COLS];                   // packed bias
__device__ __nv_bfloat16 g_Eh[2048 * EE];              // emb_table split (padded to 2048 rows)
__device__ __nv_bfloat16 g_El[2048 * EE];
__device__ float         g_ptab[(size_t)VOCAB * COLS]; // emb_table @ Wx + bias
__device__ __nv_bfloat16 g_Ah[2][(size_t)MAXMR * HH];  // hsum split, double-buffered by level parity
__device__ __nv_bfloat16 g_Al[2][(size_t)MAXMR * HH];
__device__ float         g_c[(size_t)BB * NNODE * HH];

// ---------------- helpers ----------------
__device__ __forceinline__ uint32_t smem_u32(const void* p) {
    uint32_t a;
    asm("{ .reg .u64 t; cvta.to.shared.u64 t, %1; cvt.u32.u64 %0, t; }" : "=r"(a) : "l"(p));
    return a;
}
__device__ __forceinline__ void cp_async16(uint32_t saddr, const void* g) {
    asm volatile("cp.async.cg.shared.global [%0], [%1], 16;"
                 :: "r"(saddr), "l"(__cvta_generic_to_global(g)) : "memory");
}
#define CP_COMMIT() asm volatile("cp.async.commit_group;" ::: "memory")
#define CP_WAIT(n)  asm volatile("cp.async.wait_group %0;" :: "n"(n) : "memory")

#define LDSM4(r, addr) \
    asm volatile("ldmatrix.sync.aligned.m8n8.x4.shared.b16 {%0,%1,%2,%3}, [%4];" \
        : "=r"((r)[0]), "=r"((r)[1]), "=r"((r)[2]), "=r"((r)[3]) : "r"(addr))

#define MMA16816(d, a, b) \
    asm volatile("mma.sync.aligned.m16n8k16.row.col.f32.bf16.bf16.f32 " \
        "{%0,%1,%2,%3}, {%4,%5,%6,%7}, {%8,%9}, {%0,%1,%2,%3};" \
        : "+f"((d)[0]), "+f"((d)[1]), "+f"((d)[2]), "+f"((d)[3]) \
        : "r"((a)[0]), "r"((a)[1]), "r"((a)[2]), "r"((a)[3]), "r"((b)[0]), "r"((b)[1]))

__device__ __forceinline__ void split2(float v, __nv_bfloat16& hi, __nv_bfloat16& lo) {
    hi = __float2bfloat16(v);
    lo = __float2bfloat16(v - __bfloat162float(hi));
}
// fast gates (MUFU-based): ~1e-7 rel error
__device__ __forceinline__ float sigf(float x)  { return __fdividef(1.f, 1.f + __expf(-x)); }
__device__ __forceinline__ float tanhff(float x){ return __fdividef(2.f, 1.f + __expf(-2.f * x)) - 1.f; }

// ---------------- coalesced transpose pack of W^T hi/lo ----------------
// Wcomb[k][n] (k<768, n<2048): n<1536 -> W_iou, else W_f
__global__ void packT_kernel(const float* __restrict__ W_iou, const float* __restrict__ W_f) {
    __shared__ float tile[32][33];
    int n0 = blockIdx.x * 32, k0 = blockIdx.y * 32;
    int tx = threadIdx.x, ty = threadIdx.y;      // (32, 8)
    #pragma unroll
    for (int j = 0; j < 4; j++) {
        int k = k0 + ty + j * 8;
        int n = n0 + tx;
        float w = (n < 3 * HH) ? W_iou[k * (3 * HH) + n] : W_f[k * HH + (n - 3 * HH)];
        tile[ty + j * 8][tx] = w;
    }
    __syncthreads();
    #pragma unroll
    for (int j = 0; j < 4; j++) {
        int n = n0 + ty + j * 8;
        int k = k0 + tx;
        float w = tile[tx][ty + j * 8];
        __nv_bfloat16 hi, lo; split2(w, hi, lo);
        g_WTh[(size_t)n * KTOT + k] = hi;
        g_WTl[(size_t)n * KTOT + k] = lo;
    }
}

// ---------------- split emb table (pad to 2048 rows) + bias pack ----------------
__global__ void esplit_kernel(const float* __restrict__ emb,
                              const float* __restrict__ b_iou, const float* __restrict__ b_f) {
    int idx = blockIdx.x * blockDim.x + threadIdx.x;   // over 2048*256
    if (idx >= 2048 * EE) return;
    int r = idx >> 8, k = idx & 255;
    float v = (r < VOCAB) ? emb[r * EE + k] : 0.f;
    __nv_bfloat16 hi, lo; split2(v, hi, lo);
    g_Eh[idx] = hi; g_El[idx] = lo;
    if (idx < COLS)
        g_bc[idx] = (idx < 3 * HH) ? b_iou[idx] : b_f[idx - 3 * HH];
}

// ---------------- leaf gates over sibling pairs; writes c + parent hsum-split (buf 0) ----------------
__global__ void leaf_gate(const int* __restrict__ ast) {
    int idx = blockIdx.x * blockDim.x + threadIdx.x;   // over 256*64*512
    if (idx >= 256 * 64 * HH) return;
    int k = idx & (HH - 1);
    int t = idx >> 9;                                  // pair*64 + b
    int b = t & 63, pr = t >> 6;                       // pair 0..255, parent = 255+pr
    int n1 = 511 + 2 * pr;                             // = 2*parent+1
    int tok1 = ast[b * NNODE + n1];
    int tok2 = ast[b * NNODE + n1 + 1];
    const float* p1 = g_ptab + (size_t)tok1 * COLS + k;
    const float* p2 = g_ptab + (size_t)tok2 * COLS + k;
    float c1 = sigf(p1[0]) * tanhff(p1[2 * HH]);
    float h1 = sigf(p1[HH]) * tanhff(c1);
    float c2 = sigf(p2[0]) * tanhff(p2[2 * HH]);
    float h2 = sigf(p2[HH]) * tanhff(c2);
    size_t gi1 = ((size_t)n1 * 64 + b) * HH + k;
    g_c[gi1] = c1;
    g_c[gi1 + 64 * HH] = c2;
    __nv_bfloat16 hi, lo; split2(h1 + h2, hi, lo);
    size_t po = (size_t)(pr * 64 + b) * HH + k;        // parent local row at level 8
    g_Ah[0][po] = hi;
    g_Al[0][po] = lo;
}

// ---------------- bf16x3 mma.sync GEMM (512 threads, 4x4 warps, 32x32 warptile) ----------------
// TABLE=true : g_ptab[0:2000, n0:n0+128] = Eh/El @ W[0:256] + bias     (K=256)
// TABLE=false: fused: act = ptab[tok] + hsum@W[256:768]; gates -> c, parent hsum-split
//              CTA covers 32 k-values x 4 gates; CTA's 128 rows = one sibling pair x 64 batches
static constexpr int STAGE_BYTES = 40960;   // 4 arrays x 128 rows x 80B
static constexpr int SMEM_TOTAL = STAGE_BYTES * 4;   // 160KB

template <int KDIM, bool TABLE>
__global__ __launch_bounds__(512, 1)
void mma_gemm(const int* __restrict__ ast, int base, int mrows, float* __restrict__ out, int rp) {
    extern __shared__ char smem[];
    const uint32_t sbase = smem_u32(smem);
    const int tid = threadIdx.x;
    const int lane = tid & 31, wid = tid >> 5;
    const int wm = wid >> 2, wn = wid & 3;      // warp grid 4(m) x 4(n)
    const int mtile = blockIdx.y;
    const int n0    = blockIdx.x * 128;         // TABLE: plain col base
    const int kbase = blockIdx.x * 32;          // FUSED: k base within H
    constexpr int NC = KDIM / 32;
    constexpr int KOFF = TABLE ? 0 : EE;

    const __nv_bfloat16* gAh = (TABLE ? g_Eh : &g_Ah[rp][0]) + (size_t)(mtile * 128) * KDIM;
    const __nv_bfloat16* gAl = (TABLE ? g_El : &g_Al[rp][0]) + (size_t)(mtile * 128) * KDIM;

    // ---- stage loader: A(hi/lo) 128x32, B(hi/lo) 128x32; 1 chunk each per thread ----
    auto load_stage = [&](int kc, int s) {
        const uint32_t sb = sbase + s * STAGE_BYTES;
        {
            int row = tid >> 2, ch = tid & 3;
            uint32_t so = row * 80 + ch * 16;
            const size_t ga = (size_t)row * KDIM + kc * 32 + ch * 8;
            cp_async16(sb + so,          gAh + ga);
            cp_async16(sb + 10240 + so,  gAl + ga);
        }
        {
            int j = tid >> 2, ch = tid & 3;
            int gn = TABLE ? (n0 + j) : (((j >> 5) << 9) + kbase + (j & 31));
            const size_t gb = (size_t)gn * KTOT + KOFF + kc * 32 + ch * 8;
            cp_async16(sb + 20480 + j * 80 + ch * 16, g_WTh + gb);
            cp_async16(sb + 30720 + j * 80 + ch * 16, g_WTl + gb);
        }
    };

    float acc[2][4][4] = {};

    load_stage(0, 0); CP_COMMIT();
    load_stage(1, 1); CP_COMMIT();
    load_stage(2, 2); CP_COMMIT();

    for (int c = 0; c < NC; c++) {
        CP_WAIT(2);
        __syncthreads();
        if (c + 3 < NC) load_stage(c + 3, (c + 3) & 3);
        CP_COMMIT();

        const uint32_t sb = sbase + (c & 3) * STAGE_BYTES;
        #pragma unroll
        for (int k16 = 0; k16 < 2; k16++) {
            uint32_t ah[2][4], al[2][4], bh[4][2], bl[4][2];
            #pragma unroll
            for (int mt = 0; mt < 2; mt++) {
                uint32_t addr = sb + (wm * 32 + mt * 16 + (lane & 15)) * 80
                              + k16 * 32 + ((lane >> 4) & 1) * 16;
                LDSM4(ah[mt], addr);
                LDSM4(al[mt], addr + 10240);
            }
            #pragma unroll
            for (int bt = 0; bt < 2; bt++) {
                int nrow = wn * 32 + bt * 16 + ((lane >> 4) & 1) * 8 + (lane & 7);
                uint32_t addr = sb + 20480 + nrow * 80 + k16 * 32 + ((lane >> 3) & 1) * 16;
                uint32_t t4[4];
                LDSM4(t4, addr);
                bh[2 * bt][0] = t4[0]; bh[2 * bt][1] = t4[1];
                bh[2 * bt + 1][0] = t4[2]; bh[2 * bt + 1][1] = t4[3];
                LDSM4(t4, addr + 10240);
                bl[2 * bt][0] = t4[0]; bl[2 * bt][1] = t4[1];
                bl[2 * bt + 1][0] = t4[2]; bl[2 * bt + 1][1] = t4[3];
            }
            #pragma unroll
            for (int mt = 0; mt < 2; mt++)
                #pragma unroll
                for (int nt = 0; nt < 4; nt++) {
                    MMA16816(acc[mt][nt], ah[mt], bh[nt]);
                    MMA16816(acc[mt][nt], ah[mt], bl[nt]);
                    MMA16816(acc[mt][nt], al[mt], bh[nt]);
                }
        }
    }

    if (TABLE) {
        // direct frag store: ptab = acc + bias
        #pragma unroll
        for (int mt = 0; mt < 2; mt++) {
            #pragma unroll
            for (int nt = 0; nt < 4; nt++) {
                int col = n0 + wn * 32 + nt * 8 + (lane & 3) * 2;
                int r0 = mtile * 128 + wm * 32 + mt * 16 + (lane >> 2);
                float b0 = g_bc[col], b1 = g_bc[col + 1];
                if (r0 < mrows) {
                    float2 v = make_float2(acc[mt][nt][0] + b0, acc[mt][nt][1] + b1);
                    *(float2*)&g_ptab[(size_t)r0 * COLS + col] = v;
                }
                if (r0 + 8 < mrows) {
                    float2 v = make_float2(acc[mt][nt][2] + b0, acc[mt][nt][3] + b1);
                    *(float2*)&g_ptab[(size_t)(r0 + 8) * COLS + col] = v;
                }
            }
        }
    } else {
        // stage acc -> smem, then fused gate + hsum-split epilogue
        __syncthreads();
        float* fbuf = (float*)smem;                  // [128][132]
        #pragma unroll
        for (int mt = 0; mt < 2; mt++) {
            #pragma unroll
            for (int nt = 0; nt < 4; nt++) {
                int col = wn * 32 + nt * 8 + (lane & 3) * 2;
                int r0 = wm * 32 + mt * 16 + (lane >> 2);
                fbuf[r0 * 132 + col]       = acc[mt][nt][0];
                fbuf[r0 * 132 + col + 1]   = acc[mt][nt][1];
                fbuf[(r0 + 8) * 132 + col]     = acc[mt][nt][2];
                fbuf[(r0 + 8) * 132 + col + 1] = acc[mt][nt][3];
            }
        }
        __syncthreads();
        if (base == 0) {
            // root: rows 0..63 valid, write out only
            for (int i = 0; i < 4; i++) {
                int e = tid + i * 512;               // 0..2047
                int b = e >> 5, q = e & 31;
                int k = kbase + q;
                int tok = ast[b * NNODE];            // node 0
                const float* p = g_ptab + (size_t)tok * COLS + k;
                const float* fr = fbuf + b * 132 + q;
                float xi = fr[0]  + p[0];
                float xo = fr[32] + p[HH];
                float xu = fr[64] + p[2 * HH];
                float xf = fr[96] + p[3 * HH];
                size_t ca = ((size_t)1 * 64 + b) * HH + k;     // children 1, 2
                float cs = g_c[ca] + g_c[ca + 64 * HH];
                float cc = fmaf(sigf(xf), cs, sigf(xi) * tanhff(xu));
                out[(size_t)b * HH + k] = sigf(xo) * tanhff(cc);
            }
        } else {
            const int node1 = base + mtile * 2;      // odd = 2p+1; sibling node1+1
            __nv_bfloat16* wAh = &g_Ah[rp ^ 1][0];
            __nv_bfloat16* wAl = &g_Al[rp ^ 1][0];
            for (int i = 0; i < 4; i++) {
                int e = tid + i * 512;               // 0..2047
                int b = e >> 5, q = e & 31;
                int k = kbase + q;
                int tok1 = ast[b * NNODE + node1];
                int tok2 = ast[b * NNODE + node1 + 1];
                const float* p1 = g_ptab + (size_t)tok1 * COLS + k;
                const float* p2 = g_ptab + (size_t)tok2 * COLS + k;
                const float* f1 = fbuf + b * 132 + q;
                const float* f2 = fbuf + (b + 64) * 132 + q;
                size_t ca = ((size_t)(2 * node1 + 1) * 64 + b) * HH + k;
                float cs1 = g_c[ca] + g_c[ca + 64 * HH];
                size_t cb = ((size_t)(2 * node1 + 3) * 64 + b) * HH + k;
                float cs2 = g_c[cb] + g_c[cb + 64 * HH];
                float cc1 = fmaf(sigf(f1[96] + p1[3 * HH]), cs1,
                                 sigf(f1[0] + p1[0]) * tanhff(f1[64] + p1[2 * HH]));
                float hh1 = sigf(f1[32] + p1[HH]) * tanhff(cc1);
                float cc2 = fmaf(sigf(f2[96] + p2[3 * HH]), cs2,
                                 sigf(f2[0] + p2[0]) * tanhff(f2[64] + p2[2 * HH]));
                float hh2 = sigf(f2[32] + p2[HH]) * tanhff(cc2);
                size_t gi1 = ((size_t)node1 * 64 + b) * HH + k;
                g_c[gi1] = cc1;
                g_c[gi1 + 64 * HH] = cc2;
                __nv_bfloat16 hi, lo; split2(hh1 + hh2, hi, lo);
                size_t po = (size_t)(mtile * 64 + b) * HH + k;   // parent local row
                wAh[po] = hi;
                wAl[po] = lo;
            }
        }
    }
}

// ---------------- launch ----------------
extern "C" void kernel_launch(void* const* d_in, const int* in_sizes, int n_in,
                              void* d_out, int out_size) {
    const int*   ast   = (const int*)d_in[0];
    // d_in[1] = parent (structurally (i-1)/2, unused)
    const float* emb   = (const float*)d_in[2];
    const float* W_iou = (const float*)d_in[3];
    const float* b_iou = (const float*)d_in[4];
    const float* W_f   = (const float*)d_in[5];
    const float* b_f   = (const float*)d_in[6];
    float* out = (float*)d_out;
    (void)in_sizes; (void)n_in; (void)out_size;

    cudaFuncSetAttribute(mma_gemm<EE, true>,  cudaFuncAttributeMaxDynamicSharedMemorySize, SMEM_TOTAL);
    cudaFuncSetAttribute(mma_gemm<HH, false>, cudaFuncAttributeMaxDynamicSharedMemorySize, SMEM_TOTAL);

    packT_kernel<<<dim3(COLS / 32, KTOT / 32), dim3(32, 8)>>>(W_iou, W_f);
    esplit_kernel<<<(2048 * EE + 255) / 256, 256>>>(emb, b_iou, b_f);

    // ptab = emb_table @ Wx + bias : M=2000 (pad 2048), K=256, N=2048
    {
        dim3 grid(COLS / 128, 16);
        mma_gemm<EE, true><<<grid, 512, SMEM_TOTAL>>>(nullptr, 0, VOCAB, nullptr, 0);
    }

    // leaves: gates + parent hsum-split into buf 0
    leaf_gate<<<(256 * 64 * HH + 255) / 256, 256>>>(ast);

    // levels 8..0: fused GEMM + gates + next-level hsum-split
    for (int d = 8; d >= 0; d--) {
        int L = 1 << d;
        int base = L - 1;
        int M = 64 * L;
        int mtiles = (M + 127) / 128;
        dim3 grid(HH / 32, mtiles);
        mma_gemm<HH, false><<<grid, 512, SMEM_TOTAL>>>(ast, base, M, (d == 0) ? out : nullptr, d & 1);
    }
}